// round 11
// baseline (speedup 1.0000x reference)
#include <cuda_runtime.h>
#include <cstdint>

// Problem constants
#define NQ   20
#define NL   8
#define BB   32
#define DIM  (1u << NQ)        // 1048576
#define NF4  (DIM / 4)         // 262144 float4s per statevector
#define TPB  256

// K2 geometry (measured best): 32 chunks x 16 batch-groups = 512 blocks
#define CHUNKS 32
#define BPG 2
#define NGRP (BB / BPG)                // 16
#define F4_PER_CHUNK (NF4 / CHUNKS)    // 8192
#define NIT 32                         // NIT*TPB == F4_PER_CHUNK; j gives qubits 10..14

// Scratch
__device__ float g_G[DIM];
__device__ float g_part[CHUNKS * NGRP * BPG * 21];

// ---- packed f32x2 helpers ----
__device__ __forceinline__ uint64_t mulx2(uint64_t a, uint64_t b) {
    uint64_t r; asm("mul.rn.f32x2 %0,%1,%2;" : "=l"(r) : "l"(a), "l"(b)); return r;
}
__device__ __forceinline__ uint64_t addx2(uint64_t a, uint64_t b) {
    uint64_t r; asm("add.rn.f32x2 %0,%1,%2;" : "=l"(r) : "l"(a), "l"(b)); return r;
}
__device__ __forceinline__ uint64_t fmx2(uint64_t a, uint64_t b, uint64_t c) {
    uint64_t r; asm("fma.rn.f32x2 %0,%1,%2,%3;" : "=l"(r) : "l"(a), "l"(b), "l"(c)); return r;
}
__device__ __forceinline__ float lo32(uint64_t v) { return __uint_as_float((unsigned)v); }
__device__ __forceinline__ float hi32(uint64_t v) { return __uint_as_float((unsigned)(v >> 32)); }

union F4U2 { uint4 u; ulonglong2 l; };

// ---------------------------------------------------------------------------
// Kernel 0: no-op. Exists ONLY to shift ncu's "-s 5 -c 1" capture window onto
// k_bitsum (4 kernels/call: launch #6 = call2's k_bitsum instead of k_prodG).
// ---------------------------------------------------------------------------
__global__ void k_nop() {}

// ---------------------------------------------------------------------------
// Kernel 1: G[i] = prod over 8 layers of noise[l,i]^2 (best measured variant)
// ---------------------------------------------------------------------------
__global__ void __launch_bounds__(TPB) k_prodG(const float* __restrict__ noise) {
    unsigned i = blockIdx.x * TPB + threadIdx.x;
    const float4* n4 = reinterpret_cast<const float4*>(noise);
    float4 v = n4[i];
    float4 g;
    g.x = v.x * v.x; g.y = v.y * v.y; g.z = v.z * v.z; g.w = v.w * v.w;
#pragma unroll
    for (int l = 1; l < NL; l++) {
        v = n4[(size_t)l * NF4 + i];
        g.x *= v.x * v.x; g.y *= v.y * v.y; g.z *= v.z * v.z; g.w *= v.w * v.w;
    }
    reinterpret_cast<float4*>(g_G)[i] = g;
}

// ---------------------------------------------------------------------------
// Kernel 2: bit-masked reduction, packed f32x2 + radix-4 tree accumulation.
// Element index i = idx*4 + r;  idx = chunk*8192 + j*256 + t,  j = j4*4 + jj.
//   qubits 0,1   <- r          (packed-lane position via T01/T23)
//   qubits 2..9  <- t bits     (smem combine by 2 warps)
//   qubit  10    <- jj bit 0 / pair level (J0)
//   qubit  11    <- jj bit 1 / quad level (J1)
//   qubits 12..14<- j4 bits    (predicated quad adds J2..J4)
//   qubits 15..19<- chunk bits (applied at write-out)
// ---------------------------------------------------------------------------
__global__ void __launch_bounds__(TPB, 4) k_bitsum(const float* __restrict__ amps) {
    const int bg    = blockIdx.x & (NGRP - 1);
    const int chunk = blockIdx.x >> 4;
    const int t     = threadIdx.x;

    const size_t sliceOff = (size_t)chunk * F4_PER_CHUNK + t;
    const ulonglong2* g4 = reinterpret_cast<const ulonglong2*>(g_G) + sliceOff;
    const uint4* a4_0 = reinterpret_cast<const uint4*>(amps)
                        + (size_t)(bg * BPG + 0) * NF4 + sliceOff;
    const uint4* a4_1 = reinterpret_cast<const uint4*>(amps)
                        + (size_t)(bg * BPG + 1) * NF4 + sliceOff;

    uint64_t T01[BPG] = {0, 0}, T23[BPG] = {0, 0};
    uint64_t J0[BPG] = {0, 0}, J1[BPG] = {0, 0}, J2[BPG] = {0, 0},
             J3[BPG] = {0, 0}, J4[BPG] = {0, 0};

#pragma unroll
    for (int j4 = 0; j4 < NIT / 4; j4++) {       // 8 groups of 4 iterations
        uint64_t sp[4][BPG];
#pragma unroll
        for (int jj = 0; jj < 4; jj++) {
            const int off = (j4 * 4 + jj) * TPB;
            ulonglong2 g = __ldg(g4 + off);               // L2-hot
            F4U2 A0, A1;
            A0.u = __ldcs(a4_0 + off);                    // streaming
            A1.u = __ldcs(a4_1 + off);
#pragma unroll
            for (int b2 = 0; b2 < BPG; b2++) {
                uint64_t a01 = b2 ? A1.l.x : A0.l.x;
                uint64_t a23 = b2 ? A1.l.y : A0.l.y;
                uint64_t t01 = mulx2(a01, a01);
                uint64_t t23 = mulx2(a23, a23);
                uint64_t w23 = mulx2(t23, g.y);
                sp[jj][b2]  = fmx2(t01, g.x, w23);        // (w0+w2, w1+w3)
                T01[b2] = fmx2(t01, g.x, T01[b2]);
                T23[b2] = addx2(T23[b2], w23);
            }
        }
#pragma unroll
        for (int b2 = 0; b2 < BPG; b2++) {
            // pair level: qubit 10 = j bit 0
            J0[b2] = addx2(J0[b2], addx2(sp[1][b2], sp[3][b2]));
            uint64_t P0 = addx2(sp[0][b2], sp[1][b2]);
            uint64_t P1 = addx2(sp[2][b2], sp[3][b2]);
            // quad level: qubit 11 = j bit 1
            J1[b2] = addx2(J1[b2], P1);
            uint64_t Q = addx2(P0, P1);
            if (j4 & 1) J2[b2] = addx2(J2[b2], Q);        // qubit 12
            if (j4 & 2) J3[b2] = addx2(J3[b2], Q);        // qubit 13
            if (j4 & 4) J4[b2] = addx2(J4[b2], Q);        // qubit 14
        }
    }

    __shared__ float sT[BPG][TPB];           // per-thread totals for t-bit combine
    __shared__ float red[TPB / 32][BPG][7];  // warp sums: q0,q1,J0..J4
    const int wid = t >> 5, lane = t & 31;

#pragma unroll
    for (int b2 = 0; b2 < BPG; b2++) {
        float S0 = lo32(T01[b2]), S1 = hi32(T01[b2]);
        float S2 = lo32(T23[b2]), S3 = hi32(T23[b2]);
        float v[7];
        v[0] = S1 + S3;                                   // qubit 0 (r=1,3)
        v[1] = S2 + S3;                                   // qubit 1 (r=2,3)
        v[2] = lo32(J0[b2]) + hi32(J0[b2]);
        v[3] = lo32(J1[b2]) + hi32(J1[b2]);
        v[4] = lo32(J2[b2]) + hi32(J2[b2]);
        v[5] = lo32(J3[b2]) + hi32(J3[b2]);
        v[6] = lo32(J4[b2]) + hi32(J4[b2]);
        sT[b2][t] = (S0 + S1) + (S2 + S3);
#pragma unroll
        for (int k = 0; k < 7; k++) {
#pragma unroll
            for (int o = 16; o > 0; o >>= 1)
                v[k] += __shfl_xor_sync(0xffffffffu, v[k], o);
        }
        if (lane == 0) {
#pragma unroll
            for (int k = 0; k < 7; k++) red[wid][b2][k] = v[k];
        }
    }
    __syncthreads();

    if (wid < BPG) {
        const int b2 = wid;
        float v[8];
#pragma unroll
        for (int k = 0; k < 8; k++) v[k] = sT[b2][lane + 32 * k];
        float tt = ((v[0] + v[1]) + (v[2] + v[3])) + ((v[4] + v[5]) + (v[6] + v[7]));
        float m[8];
        m[5] = (v[1] + v[3]) + (v[5] + v[7]);             // t' bit 5 -> qubit 7
        m[6] = (v[2] + v[3]) + (v[6] + v[7]);             // t' bit 6 -> qubit 8
        m[7] = (v[4] + v[5]) + (v[6] + v[7]);             // t' bit 7 -> qubit 9
#pragma unroll
        for (int k = 0; k < 5; k++)
            m[k] = ((lane >> k) & 1) ? tt : 0.f;
#pragma unroll
        for (int o = 16; o > 0; o >>= 1) {
            tt += __shfl_xor_sync(0xffffffffu, tt, o);
#pragma unroll
            for (int k = 0; k < 8; k++)
                m[k] += __shfl_xor_sync(0xffffffffu, m[k], o);
        }
        if (lane == 0) {
            float q[21];
#pragma unroll
            for (int k = 0; k < 7; k++) {
                float s = 0.f;
#pragma unroll
                for (int w = 0; w < TPB / 32; w++) s += red[w][b2][k];
                q[(k < 2) ? k : (8 + k)] = s;             // q0,q1, q10..q14
            }
#pragma unroll
            for (int k = 0; k < 8; k++) q[2 + k] = m[k];  // qubits 2..9
#pragma unroll
            for (int k = 0; k < 5; k++)
                q[15 + k] = ((chunk >> k) & 1) ? tt : 0.f;
            q[20] = tt;
            float* dst = &g_part[(size_t)blockIdx.x * (BPG * 21) + b2 * 21];
#pragma unroll
            for (int k = 0; k < 21; k++) dst[k] = q[k];
        }
    }
}

// ---------------------------------------------------------------------------
// Kernel 3: reduce partials -> qubit probs -> tanh(qp @ Wi + bi)
// ---------------------------------------------------------------------------
__global__ void k_final(const float* __restrict__ Wi, const float* __restrict__ bi,
                        float* __restrict__ out) {
    __shared__ float Q[BB][21];
    const int t = threadIdx.x;
    if (t < BB * 21) {
        const int b = t / 21, k = t % 21;
        const int bg = b >> 1, b2 = b & 1;
        float s = 0.f;
#pragma unroll
        for (int c = 0; c < CHUNKS; c++)
            s += g_part[(size_t)(c * NGRP + bg) * (BPG * 21) + b2 * 21 + k];
        Q[b][k] = s;
    }
    __syncthreads();
    if (t < BB * NQ) {
        const int b = t / NQ, j = t % NQ;
        const float inv = 1.f / Q[b][20];
        float acc = bi[j];
#pragma unroll
        for (int q = 0; q < NQ; q++) acc += (Q[b][q] * inv) * Wi[q * NQ + j];
        out[t] = tanhf(acc);
    }
}

// ---------------------------------------------------------------------------
// Launch: 4 graph-capturable kernels (k_nop is profiling ballast).
// ---------------------------------------------------------------------------
extern "C" void kernel_launch(void* const* d_in, const int* in_sizes, int n_in,
                              void* d_out, int out_size) {
    int i_amps = 7, i_noise = 8, i_Wi = 9, i_bi = 10;
    for (int i = 0; i < n_in; i++) {
        const long sz = in_sizes[i];
        if (sz == (long)BB * (long)DIM)      i_amps  = i;
        else if (sz == (long)NL * (long)DIM) i_noise = i;
        else if (sz == NQ * NQ)              i_Wi    = i;
        else if (sz == NQ)                   i_bi    = i;
    }

    const float* noise = (const float*)d_in[i_noise];
    const float* amps  = (const float*)d_in[i_amps];
    const float* Wi    = (const float*)d_in[i_Wi];
    const float* bi    = (const float*)d_in[i_bi];
    float* out         = (float*)d_out;

    k_nop   <<<1, 32>>>();                      // shifts ncu capture onto k_bitsum
    k_prodG <<<NF4 / TPB, TPB>>>(noise);
    k_bitsum<<<CHUNKS * NGRP, TPB>>>(amps);
    k_final <<<1, BB * 21>>>(Wi, bi, out);
}

// round 12
// speedup vs baseline: 1.0146x; 1.0146x over previous
#include <cuda_runtime.h>
#include <cstdint>

// Problem constants
#define NQ   20
#define NL   8
#define BB   32
#define DIM  (1u << NQ)        // 1048576
#define NF4  (DIM / 4)         // 262144 float4s per statevector
#define TPB  256

// K2 geometry (measured best): 32 chunks x 16 batch-groups = 512 blocks
#define CHUNKS 32
#define BPG 2
#define NGRP (BB / BPG)                // 16
#define F4_PER_CHUNK (NF4 / CHUNKS)    // 8192
#define NIT 32                         // NIT*TPB == F4_PER_CHUNK

// Scratch
__device__ float g_G[DIM];
__device__ float g_part[CHUNKS * NGRP * BPG * 21];

// ---- packed f32x2 helpers ----
__device__ __forceinline__ uint64_t mulx2(uint64_t a, uint64_t b) {
    uint64_t r; asm("mul.rn.f32x2 %0,%1,%2;" : "=l"(r) : "l"(a), "l"(b)); return r;
}
__device__ __forceinline__ uint64_t addx2(uint64_t a, uint64_t b) {
    uint64_t r; asm("add.rn.f32x2 %0,%1,%2;" : "=l"(r) : "l"(a), "l"(b)); return r;
}
__device__ __forceinline__ uint64_t fmx2(uint64_t a, uint64_t b, uint64_t c) {
    uint64_t r; asm("fma.rn.f32x2 %0,%1,%2,%3;" : "=l"(r) : "l"(a), "l"(b), "l"(c)); return r;
}
__device__ __forceinline__ float lo32(uint64_t v) { return __uint_as_float((unsigned)v); }
__device__ __forceinline__ float hi32(uint64_t v) { return __uint_as_float((unsigned)(v >> 32)); }

union F4U2 { uint4 u; ulonglong2 l; };

// ---------------------------------------------------------------------------
// Kernel 1: G[i] = prod over 8 layers of noise[l,i]^2 (best measured variant)
// ---------------------------------------------------------------------------
__global__ void __launch_bounds__(TPB) k_prodG(const float* __restrict__ noise) {
    unsigned i = blockIdx.x * TPB + threadIdx.x;
    const float4* n4 = reinterpret_cast<const float4*>(noise);
    float4 v = n4[i];
    float4 g;
    g.x = v.x * v.x; g.y = v.y * v.y; g.z = v.z * v.z; g.w = v.w * v.w;
#pragma unroll
    for (int l = 1; l < NL; l++) {
        v = n4[(size_t)l * NF4 + i];
        g.x *= v.x * v.x; g.y *= v.y * v.y; g.z *= v.z * v.z; g.w *= v.w * v.w;
    }
    reinterpret_cast<float4*>(g_G)[i] = g;
}

// ---------------------------------------------------------------------------
// Kernel 2: bit-masked reduction, packed f32x2 + radix-4 tree (R10, ~17.5us
// = ~7.3 TB/s on the amps stream -> DRAM-saturated, do not touch).
// ---------------------------------------------------------------------------
__global__ void __launch_bounds__(TPB, 4) k_bitsum(const float* __restrict__ amps) {
    const int bg    = blockIdx.x & (NGRP - 1);
    const int chunk = blockIdx.x >> 4;
    const int t     = threadIdx.x;

    const size_t sliceOff = (size_t)chunk * F4_PER_CHUNK + t;
    const ulonglong2* g4 = reinterpret_cast<const ulonglong2*>(g_G) + sliceOff;
    const uint4* a4_0 = reinterpret_cast<const uint4*>(amps)
                        + (size_t)(bg * BPG + 0) * NF4 + sliceOff;
    const uint4* a4_1 = reinterpret_cast<const uint4*>(amps)
                        + (size_t)(bg * BPG + 1) * NF4 + sliceOff;

    uint64_t T01[BPG] = {0, 0}, T23[BPG] = {0, 0};
    uint64_t J0[BPG] = {0, 0}, J1[BPG] = {0, 0}, J2[BPG] = {0, 0},
             J3[BPG] = {0, 0}, J4[BPG] = {0, 0};

#pragma unroll
    for (int j4 = 0; j4 < NIT / 4; j4++) {
        uint64_t sp[4][BPG];
#pragma unroll
        for (int jj = 0; jj < 4; jj++) {
            const int off = (j4 * 4 + jj) * TPB;
            ulonglong2 g = __ldg(g4 + off);               // L2-hot
            F4U2 A0, A1;
            A0.u = __ldcs(a4_0 + off);                    // streaming
            A1.u = __ldcs(a4_1 + off);
#pragma unroll
            for (int b2 = 0; b2 < BPG; b2++) {
                uint64_t a01 = b2 ? A1.l.x : A0.l.x;
                uint64_t a23 = b2 ? A1.l.y : A0.l.y;
                uint64_t t01 = mulx2(a01, a01);
                uint64_t t23 = mulx2(a23, a23);
                uint64_t w23 = mulx2(t23, g.y);
                sp[jj][b2]  = fmx2(t01, g.x, w23);        // (w0+w2, w1+w3)
                T01[b2] = fmx2(t01, g.x, T01[b2]);
                T23[b2] = addx2(T23[b2], w23);
            }
        }
#pragma unroll
        for (int b2 = 0; b2 < BPG; b2++) {
            J0[b2] = addx2(J0[b2], addx2(sp[1][b2], sp[3][b2]));   // qubit 10
            uint64_t P0 = addx2(sp[0][b2], sp[1][b2]);
            uint64_t P1 = addx2(sp[2][b2], sp[3][b2]);
            J1[b2] = addx2(J1[b2], P1);                            // qubit 11
            uint64_t Q = addx2(P0, P1);
            if (j4 & 1) J2[b2] = addx2(J2[b2], Q);                 // qubit 12
            if (j4 & 2) J3[b2] = addx2(J3[b2], Q);                 // qubit 13
            if (j4 & 4) J4[b2] = addx2(J4[b2], Q);                 // qubit 14
        }
    }

    __shared__ float sT[BPG][TPB];
    __shared__ float red[TPB / 32][BPG][7];
    const int wid = t >> 5, lane = t & 31;

#pragma unroll
    for (int b2 = 0; b2 < BPG; b2++) {
        float S0 = lo32(T01[b2]), S1 = hi32(T01[b2]);
        float S2 = lo32(T23[b2]), S3 = hi32(T23[b2]);
        float v[7];
        v[0] = S1 + S3;                                   // qubit 0
        v[1] = S2 + S3;                                   // qubit 1
        v[2] = lo32(J0[b2]) + hi32(J0[b2]);
        v[3] = lo32(J1[b2]) + hi32(J1[b2]);
        v[4] = lo32(J2[b2]) + hi32(J2[b2]);
        v[5] = lo32(J3[b2]) + hi32(J3[b2]);
        v[6] = lo32(J4[b2]) + hi32(J4[b2]);
        sT[b2][t] = (S0 + S1) + (S2 + S3);
#pragma unroll
        for (int k = 0; k < 7; k++) {
#pragma unroll
            for (int o = 16; o > 0; o >>= 1)
                v[k] += __shfl_xor_sync(0xffffffffu, v[k], o);
        }
        if (lane == 0) {
#pragma unroll
            for (int k = 0; k < 7; k++) red[wid][b2][k] = v[k];
        }
    }
    __syncthreads();

    if (wid < BPG) {
        const int b2 = wid;
        float v[8];
#pragma unroll
        for (int k = 0; k < 8; k++) v[k] = sT[b2][lane + 32 * k];
        float tt = ((v[0] + v[1]) + (v[2] + v[3])) + ((v[4] + v[5]) + (v[6] + v[7]));
        float m[8];
        m[5] = (v[1] + v[3]) + (v[5] + v[7]);             // qubit 7
        m[6] = (v[2] + v[3]) + (v[6] + v[7]);             // qubit 8
        m[7] = (v[4] + v[5]) + (v[6] + v[7]);             // qubit 9
#pragma unroll
        for (int k = 0; k < 5; k++)
            m[k] = ((lane >> k) & 1) ? tt : 0.f;          // qubits 2..6
#pragma unroll
        for (int o = 16; o > 0; o >>= 1) {
            tt += __shfl_xor_sync(0xffffffffu, tt, o);
#pragma unroll
            for (int k = 0; k < 8; k++)
                m[k] += __shfl_xor_sync(0xffffffffu, m[k], o);
        }
        if (lane == 0) {
            float q[21];
#pragma unroll
            for (int k = 0; k < 7; k++) {
                float s = 0.f;
#pragma unroll
                for (int w = 0; w < TPB / 32; w++) s += red[w][b2][k];
                q[(k < 2) ? k : (8 + k)] = s;             // q0,q1, q10..q14
            }
#pragma unroll
            for (int k = 0; k < 8; k++) q[2 + k] = m[k];  // qubits 2..9
#pragma unroll
            for (int k = 0; k < 5; k++)
                q[15 + k] = ((chunk >> k) & 1) ? tt : 0.f;
            q[20] = tt;
            float* dst = &g_part[(size_t)blockIdx.x * (BPG * 21) + b2 * 21];
#pragma unroll
            for (int k = 0; k < 21; k++) dst[k] = q[k];
        }
    }
}

// ---------------------------------------------------------------------------
// Kernel 3 (REWRITE): one block per batch, 672 threads = 32 chunks x 21 vals,
// ONE coalesced-ish load per thread, smem tree over the chunk dim, matvec.
// ---------------------------------------------------------------------------
__global__ void __launch_bounds__(672) k_final(const float* __restrict__ Wi,
                                               const float* __restrict__ bi,
                                               float* __restrict__ out) {
    const int b  = blockIdx.x;          // batch 0..31
    const int bg = b >> 1, b2 = b & 1;
    const int t  = threadIdx.x;         // t = c*21 + k
    const int c  = t / 21, k = t % 21;

    __shared__ float sm[CHUNKS * 21];
    sm[t] = __ldg(&g_part[(size_t)(c * NGRP + bg) * (BPG * 21) + b2 * 21 + k]);
    __syncthreads();

    // tree-reduce the chunk dimension: 32 -> 1
#pragma unroll
    for (int step = CHUNKS / 2; step >= 1; step >>= 1) {
        if (c < step) sm[c * 21 + k] += sm[(c + step) * 21 + k];
        __syncthreads();
    }

    if (t < NQ) {
        const float inv = 1.f / sm[20];
        float acc = bi[t];
#pragma unroll
        for (int q = 0; q < NQ; q++) acc += (sm[q] * inv) * Wi[q * NQ + t];
        out[b * NQ + t] = tanhf(acc);
    }
}

// ---------------------------------------------------------------------------
// Launch: 3 graph-capturable kernels, no syncs, no allocations.
// ---------------------------------------------------------------------------
extern "C" void kernel_launch(void* const* d_in, const int* in_sizes, int n_in,
                              void* d_out, int out_size) {
    int i_amps = 7, i_noise = 8, i_Wi = 9, i_bi = 10;
    for (int i = 0; i < n_in; i++) {
        const long sz = in_sizes[i];
        if (sz == (long)BB * (long)DIM)      i_amps  = i;
        else if (sz == (long)NL * (long)DIM) i_noise = i;
        else if (sz == NQ * NQ)              i_Wi    = i;
        else if (sz == NQ)                   i_bi    = i;
    }

    const float* noise = (const float*)d_in[i_noise];
    const float* amps  = (const float*)d_in[i_amps];
    const float* Wi    = (const float*)d_in[i_Wi];
    const float* bi    = (const float*)d_in[i_bi];
    float* out         = (float*)d_out;

    k_prodG <<<NF4 / TPB, TPB>>>(noise);        // 1024 blocks
    k_bitsum<<<CHUNKS * NGRP, TPB>>>(amps);     //  512 blocks (DRAM-saturated)
    k_final <<<BB, 672>>>(Wi, bi, out);         //   32 blocks, 1 load/thread
}